// round 9
// baseline (speedup 1.0000x reference)
#include <cuda_runtime.h>
#include <cuda_bf16.h>
#include <cstdint>

// Decoder (Conv-TasNet): out = overlap_add( (mixture_w * est_mask)^T @ W^T, step=L/2 )
// mixture_w/est_mask [B, N, K] f32, W [L, N] f32, out [B, T] f32
// B=4, N=512, K=16000, L=16, step=8, T = 8*(K-1)+16 = 128008
//
// R9: KPT=4 + LDG.128. Four frames per thread amortize the W shared-memory
// reads (LDS.128 per k*n halves vs KPT=2 -- the crossbar was ~50% busy) and
// halve LDG count while doubling lines-in-flight per load. FFMA2 throughout.

#define DEC_B 4
#define DEC_N 512
#define DEC_K 16000
#define DEC_L 16
#define DEC_STEP 8
#define DEC_T (DEC_STEP * (DEC_K - 1) + DEC_L)   // 128008

#define TPB 64
#define NSPLIT 4
#define NCHUNK (DEC_N / NSPLIT)      // 128
#define KPT 4                         // frames per thread (float4 along k)
#define NB 4                          // n's per load batch (8 LDG.128 in flight)
#define NACC 20                       // f32x2 accumulators (40 out positions)

typedef unsigned long long u64t;

#define FMA_F32X2(d, a, b, c) \
    asm("fma.rn.f32x2 %0, %1, %2, %3;" : "=l"(d) : "l"(a), "l"(b), "l"(c))

__global__ __launch_bounds__(TPB)
void decoder_kernel(const float* __restrict__ mw,
                    const float* __restrict__ em,
                    const float* __restrict__ W,
                    float* __restrict__ out)
{
    // This block's N-chunk of W, transposed: Ws[n_local][l]. 8 KB.
    __shared__ __align__(16) float Ws[NCHUNK * DEC_L];
    const int nb = blockIdx.z * NCHUNK;
    for (int i = threadIdx.x; i < NCHUNK * DEC_L; i += TPB) {
        int n = i >> 4;
        int l = i & 15;
        Ws[i] = W[l * DEC_N + nb + n];
    }
    __syncthreads();

    const int b  = blockIdx.y;
    const int k0 = (blockIdx.x * TPB + threadIdx.x) * KPT;
    if (k0 >= DEC_K) return;   // tail guard (63*64*4 = 16128 > 16000; K%4==0)

    const size_t base = (size_t)b * DEC_N * DEC_K + (size_t)nb * DEC_K + k0;
    const float4* __restrict__ mwp = reinterpret_cast<const float4*>(mw + base);
    const float4* __restrict__ emp = reinterpret_cast<const float4*>(em + base);
    const size_t kstr = DEC_K / 4;   // float4 stride between n rows

    // 40 fp32 out positions as 20 f32x2 pairs. Frame fi (i=0..3) covers
    // positions 8i..8i+15 = pairs 4i..4i+7.
    u64t accp[NACC];
#pragma unroll
    for (int i = 0; i < NACC; ++i) accp[i] = 0ull;

    // One n-step: 4 FMUL + 4 packs + 4 LDS.128 + 32 FFMA2, serving 4 frames.
    auto step = [&](int n, float4 m, float4 e) {
        float p[KPT];
        p[0] = m.x * e.x;
        p[1] = m.y * e.y;
        p[2] = m.z * e.z;
        p[3] = m.w * e.w;
        u64t pp[KPT];
#pragma unroll
        for (int f = 0; f < KPT; ++f)
            asm("mov.b64 %0, {%1, %1};" : "=l"(pp[f]) : "f"(p[f]));

        const ulonglong2* wq = reinterpret_cast<const ulonglong2*>(&Ws[n * DEC_L]);
        ulonglong2 wa = wq[0];
        ulonglong2 wb = wq[1];
        ulonglong2 wc = wq[2];
        ulonglong2 wd = wq[3];
        u64t w[8] = { wa.x, wa.y, wb.x, wb.y, wc.x, wc.y, wd.x, wd.y };

#pragma unroll
        for (int f = 0; f < KPT; ++f) {
#pragma unroll
            for (int j = 0; j < 8; ++j) {
                FMA_F32X2(accp[4 * f + j], w[j], pp[f], accp[4 * f + j]);
            }
        }
    };

    for (int n0 = 0; n0 < NCHUNK; n0 += NB) {
        // Batch: 8 independent coalesced streaming LDG.128s (32 lines in flight).
        float4 m[NB], e[NB];
#pragma unroll
        for (int j = 0; j < NB; ++j) {
            m[j] = __ldcs(&mwp[(size_t)(n0 + j) * kstr]);
            e[j] = __ldcs(&emp[(size_t)(n0 + j) * kstr]);
        }
#pragma unroll
        for (int j = 0; j < NB; ++j) step(n0 + j, m[j], e[j]);
    }

    // Scatter-add 40 unique positions (frames k0..k0+3). Interior overlaps
    // merged in registers; each out element gets <= 2*NSPLIT = 8 atomic fp32
    // contributions (order-insensitive).
    float* __restrict__ op = out + (size_t)b * DEC_T + (size_t)k0 * DEC_STEP;
#pragma unroll
    for (int i = 0; i < NACC; ++i) {
        float lo, hi;
        asm("mov.b64 {%0, %1}, %2;" : "=f"(lo), "=f"(hi) : "l"(accp[i]));
        atomicAdd(&op[2 * i],     lo);
        atomicAdd(&op[2 * i + 1], hi);
    }
}

extern "C" void kernel_launch(void* const* d_in, const int* in_sizes, int n_in,
                              void* d_out, int out_size)
{
    const float* mixture_w = (const float*)d_in[0];  // [B, N, K]
    const float* est_mask  = (const float*)d_in[1];  // [B, N, K]
    const float* W         = (const float*)d_in[2];  // [L, N]
    float* out = (float*)d_out;                       // [B, T]

    cudaMemsetAsync(out, 0, (size_t)out_size * sizeof(float), 0);

    dim3 grid((DEC_K + TPB * KPT - 1) / (TPB * KPT), DEC_B, NSPLIT);  // (63, 4, 4)
    decoder_kernel<<<grid, TPB>>>(mixture_w, est_mask, W, out);
}